// round 1
// baseline (speedup 1.0000x reference)
#include <cuda_runtime.h>
#include <cstdint>

#define D 128
#define NNODES 50000
#define NEDGES 600000
#define BM 64
#define THREADS 256

// Scratch (allocation-free rule: device globals)
__device__ float g_x[(size_t)NNODES * D];   // x = h + segment_sum(h[src], dst)
__device__ float g_h[(size_t)NNODES * D];   // layer-1 output

// ---------------------------------------------------------------------------
// copy: dst = src (vectorized)
// ---------------------------------------------------------------------------
__global__ void k_copy(const float* __restrict__ src, float* __restrict__ dst, int n4) {
    int i = blockIdx.x * blockDim.x + threadIdx.x;
    if (i < n4) ((float4*)dst)[i] = ((const float4*)src)[i];
}

// ---------------------------------------------------------------------------
// scatter: x[dst[e]] += h[src[e]]   (one warp per edge, one red.v4 per lane)
// ---------------------------------------------------------------------------
__global__ void k_scatter(const float* __restrict__ h,
                          const int* __restrict__ src,
                          const int* __restrict__ dst) {
    int gid  = blockIdx.x * blockDim.x + threadIdx.x;
    int e    = gid >> 5;
    int lane = gid & 31;
    if (e >= NEDGES) return;
    int s = src[e];
    int d = dst[e];
    const float4* hp = (const float4*)(h + (size_t)s * D);
    float4 v = hp[lane];
    float* xp = g_x + (size_t)d * D + lane * 4;
    asm volatile("red.global.add.v4.f32 [%0], {%1,%2,%3,%4};"
                 :: "l"(xp), "f"(v.x), "f"(v.y), "f"(v.z), "f"(v.w)
                 : "memory");
}

// ---------------------------------------------------------------------------
// fused MLP: out = maybe_relu( relu(x @ Wa + ba) @ Wb + bb )
// Block: BM=64 rows, full 128 cols. Wa+Wb resident in smem (128KB),
// x-tile + h-tile 64KB. 256 threads, each computes a 4x8 microtile.
// ---------------------------------------------------------------------------
__global__ __launch_bounds__(THREADS, 1)
void k_mlp(const float* __restrict__ x,
           const float* __restrict__ Wa, const float* __restrict__ ba,
           const float* __restrict__ Wb, const float* __restrict__ bb,
           float* __restrict__ out, int relu_out) {
    extern __shared__ float smem[];
    float* sWa = smem;                      // D*D
    float* sWb = smem + D * D;              // D*D
    float* sX  = smem + 2 * D * D;          // BM*D
    float* sH  = smem + 2 * D * D + BM * D; // BM*D

    const int tid  = threadIdx.x;
    const int row0 = blockIdx.x * BM;

    // load weights
    {
        const float4* Wa4 = (const float4*)Wa;
        const float4* Wb4 = (const float4*)Wb;
        float4* sWa4 = (float4*)sWa;
        float4* sWb4 = (float4*)sWb;
        #pragma unroll
        for (int i = tid; i < D * D / 4; i += THREADS) {
            sWa4[i] = Wa4[i];
            sWb4[i] = Wb4[i];
        }
    }
    // load x tile (zero-pad past NNODES)
    for (int i = tid; i < BM * D / 4; i += THREADS) {
        int r = i / (D / 4);
        float4 v = make_float4(0.f, 0.f, 0.f, 0.f);
        if (row0 + r < NNODES)
            v = ((const float4*)(x + (size_t)(row0 + r) * D))[i % (D / 4)];
        ((float4*)sX)[i] = v;
    }
    __syncthreads();

    const int tx = tid & 15;        // col group
    const int ty = tid >> 4;        // row group
    const int rbase = ty * 4;
    const int cbase = tx * 8;

    float acc[4][8];

    // ---- GEMM1: h = relu(x @ Wa + ba) ----
    #pragma unroll
    for (int i = 0; i < 4; i++)
        #pragma unroll
        for (int j = 0; j < 8; j++) acc[i][j] = 0.f;

    #pragma unroll 4
    for (int k = 0; k < D; ++k) {
        float a[4];
        #pragma unroll
        for (int i = 0; i < 4; i++) a[i] = sX[(rbase + i) * D + k];
        float4 b0 = *(const float4*)&sWa[k * D + cbase];
        float4 b1 = *(const float4*)&sWa[k * D + cbase + 4];
        float b[8] = {b0.x, b0.y, b0.z, b0.w, b1.x, b1.y, b1.z, b1.w};
        #pragma unroll
        for (int i = 0; i < 4; i++)
            #pragma unroll
            for (int j = 0; j < 8; j++)
                acc[i][j] = fmaf(a[i], b[j], acc[i][j]);
    }

    float bav[8];
    #pragma unroll
    for (int j = 0; j < 8; j++) bav[j] = __ldg(&ba[cbase + j]);
    #pragma unroll
    for (int i = 0; i < 4; i++)
        #pragma unroll
        for (int j = 0; j < 8; j++)
            sH[(rbase + i) * D + cbase + j] = fmaxf(acc[i][j] + bav[j], 0.f);
    __syncthreads();

    // ---- GEMM2: y = h @ Wb + bb ----
    #pragma unroll
    for (int i = 0; i < 4; i++)
        #pragma unroll
        for (int j = 0; j < 8; j++) acc[i][j] = 0.f;

    #pragma unroll 4
    for (int k = 0; k < D; ++k) {
        float a[4];
        #pragma unroll
        for (int i = 0; i < 4; i++) a[i] = sH[(rbase + i) * D + k];
        float4 b0 = *(const float4*)&sWb[k * D + cbase];
        float4 b1 = *(const float4*)&sWb[k * D + cbase + 4];
        float b[8] = {b0.x, b0.y, b0.z, b0.w, b1.x, b1.y, b1.z, b1.w};
        #pragma unroll
        for (int i = 0; i < 4; i++)
            #pragma unroll
            for (int j = 0; j < 8; j++)
                acc[i][j] = fmaf(a[i], b[j], acc[i][j]);
    }

    float bbv[8];
    #pragma unroll
    for (int j = 0; j < 8; j++) bbv[j] = __ldg(&bb[cbase + j]);

    #pragma unroll
    for (int i = 0; i < 4; i++) {
        int row = row0 + rbase + i;
        if (row >= NNODES) break;
        float4 o0, o1;
        float v[8];
        #pragma unroll
        for (int j = 0; j < 8; j++) {
            v[j] = acc[i][j] + bbv[j];
            if (relu_out) v[j] = fmaxf(v[j], 0.f);
        }
        o0 = make_float4(v[0], v[1], v[2], v[3]);
        o1 = make_float4(v[4], v[5], v[6], v[7]);
        float4* op = (float4*)(out + (size_t)row * D + cbase);
        op[0] = o0;
        op[1] = o1;
    }
}

// ---------------------------------------------------------------------------
// launch
// ---------------------------------------------------------------------------
extern "C" void kernel_launch(void* const* d_in, const int* in_sizes, int n_in,
                              void* d_out, int out_size) {
    const float* inputs = (const float*)d_in[0];
    const int*   src    = (const int*)  d_in[1];
    const int*   dst    = (const int*)  d_in[2];
    const float* W1a    = (const float*)d_in[3];
    const float* b1a    = (const float*)d_in[4];
    const float* W1b    = (const float*)d_in[5];
    const float* b1b    = (const float*)d_in[6];
    const float* W2a    = (const float*)d_in[7];
    const float* b2a    = (const float*)d_in[8];
    const float* W2b    = (const float*)d_in[9];
    const float* b2b    = (const float*)d_in[10];
    float* out = (float*)d_out;

    float *gx = nullptr, *gh = nullptr;
    cudaGetSymbolAddress((void**)&gx, g_x);
    cudaGetSymbolAddress((void**)&gh, g_h);

    const int smem_bytes = (2 * D * D + 2 * BM * D) * sizeof(float); // 192 KB
    static bool attr_set = false;
    // setting an attribute is idempotent; do it every call to stay stateless
    cudaFuncSetAttribute(k_mlp, cudaFuncAttributeMaxDynamicSharedMemorySize, smem_bytes);
    (void)attr_set;

    const int n4 = NNODES * D / 4;
    const int copy_blocks = (n4 + 255) / 256;
    const int scat_blocks = (NEDGES * 32 + THREADS - 1) / THREADS;
    const int mlp_blocks  = (NNODES + BM - 1) / BM;

    // ---- layer 1 ----
    k_copy<<<copy_blocks, 256>>>(inputs, gx, n4);
    k_scatter<<<scat_blocks, THREADS>>>(inputs, src, dst);
    k_mlp<<<mlp_blocks, THREADS, smem_bytes>>>(gx, W1a, b1a, W1b, b1b, gh, 1);

    // ---- layer 2 ----
    k_copy<<<copy_blocks, 256>>>(gh, gx, n4);
    k_scatter<<<scat_blocks, THREADS>>>(gh, src, dst);
    k_mlp<<<mlp_blocks, THREADS, smem_bytes>>>(gx, W2a, b2a, W2b, b2b, out, 0);
}

// round 2
// speedup vs baseline: 1.1353x; 1.1353x over previous
#include <cuda_runtime.h>
#include <cstdint>

#define D 128
#define NNODES 50000
#define NEDGES 600000
#define BM 64
#define THREADS 256

// ---------------------------------------------------------------------------
// Scratch (allocation-free rule: device globals)
// ---------------------------------------------------------------------------
__device__ float g_x[(size_t)NNODES * D];     // x = h + segment_sum(h[src], dst)
__device__ float g_h[(size_t)NNODES * D];     // layer-1 output
__device__ int   g_deg[NNODES];               // in-degree histogram
__device__ int   g_off[NNODES + 1];           // CSR offsets (exclusive scan)
__device__ int   g_cursor[NNODES];            // fill cursors
__device__ int   g_adj[NEDGES];               // CSR adjacency: src node per slot

// ---------------------------------------------------------------------------
// histogram: deg[dst[e]] += 1
// ---------------------------------------------------------------------------
__global__ void k_hist(const int* __restrict__ dst) {
    int e = blockIdx.x * blockDim.x + threadIdx.x;
    if (e < NEDGES) atomicAdd(&g_deg[dst[e]], 1);
}

// ---------------------------------------------------------------------------
// single-block exclusive scan of deg -> off (and cursor copy)
// 1024 threads, chunked Hillis-Steele via warp shuffles
// ---------------------------------------------------------------------------
__global__ __launch_bounds__(1024, 1)
void k_scan() {
    __shared__ int warp_sums[32];
    __shared__ int carry_s;
    const int tid  = threadIdx.x;
    const int lane = tid & 31;
    const int wid  = tid >> 5;
    if (tid == 0) carry_s = 0;
    __syncthreads();

    for (int base = 0; base < NNODES; base += 1024) {
        int i = base + tid;
        int v = (i < NNODES) ? g_deg[i] : 0;
        // inclusive warp scan
        int s = v;
        #pragma unroll
        for (int o = 1; o < 32; o <<= 1) {
            int t = __shfl_up_sync(0xFFFFFFFFu, s, o);
            if (lane >= o) s += t;
        }
        if (lane == 31) warp_sums[wid] = s;
        __syncthreads();
        if (wid == 0) {
            int ws = warp_sums[lane];
            #pragma unroll
            for (int o = 1; o < 32; o <<= 1) {
                int t = __shfl_up_sync(0xFFFFFFFFu, ws, o);
                if (lane >= o) ws += t;
            }
            warp_sums[lane] = ws;
        }
        __syncthreads();
        int carry = carry_s;
        int excl  = carry + (wid ? warp_sums[wid - 1] : 0) + s - v;
        if (i < NNODES) {
            g_off[i]    = excl;
            g_cursor[i] = excl;
        }
        __syncthreads();                    // everyone done reading carry_s
        if (tid == 1023) carry_s = carry + warp_sums[31];
        __syncthreads();
    }
    if (tid == 0) g_off[NNODES] = carry_s;  // == NEDGES
}

// ---------------------------------------------------------------------------
// fill CSR adjacency: slot <- src[e], segmented by dst[e]
// ---------------------------------------------------------------------------
__global__ void k_fill(const int* __restrict__ src, const int* __restrict__ dst) {
    int e = blockIdx.x * blockDim.x + threadIdx.x;
    if (e < NEDGES) {
        int pos = atomicAdd(&g_cursor[dst[e]], 1);
        g_adj[pos] = src[e];
    }
}

// ---------------------------------------------------------------------------
// gather: x[i] = h[i] + sum_{s in adj(i)} h[s]   (one warp per node)
// lane l owns float4 column chunk l; rows are coalesced 512B reads
// ---------------------------------------------------------------------------
__global__ __launch_bounds__(THREADS)
void k_gather(const float* __restrict__ h, float* __restrict__ x) {
    int warp = (blockIdx.x * blockDim.x + threadIdx.x) >> 5;
    int lane = threadIdx.x & 31;
    if (warp >= NNODES) return;
    const float4* hp = (const float4*)h;
    int beg = g_off[warp];
    int end = g_off[warp + 1];

    float4 acc = hp[(size_t)warp * 32 + lane];

    int p = beg;
    // 4-way batched: 4 outstanding row loads per iteration
    for (; p + 4 <= end; p += 4) {
        int s0 = g_adj[p + 0];
        int s1 = g_adj[p + 1];
        int s2 = g_adj[p + 2];
        int s3 = g_adj[p + 3];
        float4 v0 = hp[(size_t)s0 * 32 + lane];
        float4 v1 = hp[(size_t)s1 * 32 + lane];
        float4 v2 = hp[(size_t)s2 * 32 + lane];
        float4 v3 = hp[(size_t)s3 * 32 + lane];
        acc.x += v0.x + v1.x + v2.x + v3.x;
        acc.y += v0.y + v1.y + v2.y + v3.y;
        acc.z += v0.z + v1.z + v2.z + v3.z;
        acc.w += v0.w + v1.w + v2.w + v3.w;
    }
    for (; p < end; ++p) {
        int s = g_adj[p];
        float4 v = hp[(size_t)s * 32 + lane];
        acc.x += v.x; acc.y += v.y; acc.z += v.z; acc.w += v.w;
    }
    ((float4*)x)[(size_t)warp * 32 + lane] = acc;
}

// ---------------------------------------------------------------------------
// fused MLP: out = maybe_relu( relu(x @ Wa + ba) @ Wb + bb )
// ---------------------------------------------------------------------------
__global__ __launch_bounds__(THREADS, 1)
void k_mlp(const float* __restrict__ x,
           const float* __restrict__ Wa, const float* __restrict__ ba,
           const float* __restrict__ Wb, const float* __restrict__ bb,
           float* __restrict__ out, int relu_out) {
    extern __shared__ float smem[];
    float* sWa = smem;                      // D*D
    float* sWb = smem + D * D;              // D*D
    float* sX  = smem + 2 * D * D;          // BM*D
    float* sH  = smem + 2 * D * D + BM * D; // BM*D

    const int tid  = threadIdx.x;
    const int row0 = blockIdx.x * BM;

    {
        const float4* Wa4 = (const float4*)Wa;
        const float4* Wb4 = (const float4*)Wb;
        float4* sWa4 = (float4*)sWa;
        float4* sWb4 = (float4*)sWb;
        #pragma unroll
        for (int i = tid; i < D * D / 4; i += THREADS) {
            sWa4[i] = Wa4[i];
            sWb4[i] = Wb4[i];
        }
    }
    for (int i = tid; i < BM * D / 4; i += THREADS) {
        int r = i / (D / 4);
        float4 v = make_float4(0.f, 0.f, 0.f, 0.f);
        if (row0 + r < NNODES)
            v = ((const float4*)(x + (size_t)(row0 + r) * D))[i % (D / 4)];
        ((float4*)sX)[i] = v;
    }
    __syncthreads();

    const int tx = tid & 15;
    const int ty = tid >> 4;
    const int rbase = ty * 4;
    const int cbase = tx * 8;

    float acc[4][8];

    // ---- GEMM1: h = relu(x @ Wa + ba) ----
    #pragma unroll
    for (int i = 0; i < 4; i++)
        #pragma unroll
        for (int j = 0; j < 8; j++) acc[i][j] = 0.f;

    #pragma unroll 4
    for (int k = 0; k < D; ++k) {
        float a[4];
        #pragma unroll
        for (int i = 0; i < 4; i++) a[i] = sX[(rbase + i) * D + k];
        float4 b0 = *(const float4*)&sWa[k * D + cbase];
        float4 b1 = *(const float4*)&sWa[k * D + cbase + 4];
        float b[8] = {b0.x, b0.y, b0.z, b0.w, b1.x, b1.y, b1.z, b1.w};
        #pragma unroll
        for (int i = 0; i < 4; i++)
            #pragma unroll
            for (int j = 0; j < 8; j++)
                acc[i][j] = fmaf(a[i], b[j], acc[i][j]);
    }

    float bav[8];
    #pragma unroll
    for (int j = 0; j < 8; j++) bav[j] = __ldg(&ba[cbase + j]);
    #pragma unroll
    for (int i = 0; i < 4; i++)
        #pragma unroll
        for (int j = 0; j < 8; j++)
            sH[(rbase + i) * D + cbase + j] = fmaxf(acc[i][j] + bav[j], 0.f);
    __syncthreads();

    // ---- GEMM2: y = h @ Wb + bb ----
    #pragma unroll
    for (int i = 0; i < 4; i++)
        #pragma unroll
        for (int j = 0; j < 8; j++) acc[i][j] = 0.f;

    #pragma unroll 4
    for (int k = 0; k < D; ++k) {
        float a[4];
        #pragma unroll
        for (int i = 0; i < 4; i++) a[i] = sH[(rbase + i) * D + k];
        float4 b0 = *(const float4*)&sWb[k * D + cbase];
        float4 b1 = *(const float4*)&sWb[k * D + cbase + 4];
        float b[8] = {b0.x, b0.y, b0.z, b0.w, b1.x, b1.y, b1.z, b1.w};
        #pragma unroll
        for (int i = 0; i < 4; i++)
            #pragma unroll
            for (int j = 0; j < 8; j++)
                acc[i][j] = fmaf(a[i], b[j], acc[i][j]);
    }

    float bbv[8];
    #pragma unroll
    for (int j = 0; j < 8; j++) bbv[j] = __ldg(&bb[cbase + j]);

    #pragma unroll
    for (int i = 0; i < 4; i++) {
        int row = row0 + rbase + i;
        if (row >= NNODES) break;
        float v[8];
        #pragma unroll
        for (int j = 0; j < 8; j++) {
            v[j] = acc[i][j] + bbv[j];
            if (relu_out) v[j] = fmaxf(v[j], 0.f);
        }
        float4* op = (float4*)(out + (size_t)row * D + cbase);
        op[0] = make_float4(v[0], v[1], v[2], v[3]);
        op[1] = make_float4(v[4], v[5], v[6], v[7]);
    }
}

// ---------------------------------------------------------------------------
// launch
// ---------------------------------------------------------------------------
extern "C" void kernel_launch(void* const* d_in, const int* in_sizes, int n_in,
                              void* d_out, int out_size) {
    const float* inputs = (const float*)d_in[0];
    const int*   src    = (const int*)  d_in[1];
    const int*   dst    = (const int*)  d_in[2];
    const float* W1a    = (const float*)d_in[3];
    const float* b1a    = (const float*)d_in[4];
    const float* W1b    = (const float*)d_in[5];
    const float* b1b    = (const float*)d_in[6];
    const float* W2a    = (const float*)d_in[7];
    const float* b2a    = (const float*)d_in[8];
    const float* W2b    = (const float*)d_in[9];
    const float* b2b    = (const float*)d_in[10];
    float* out = (float*)d_out;

    float *gx = nullptr, *gh = nullptr;
    int   *gdeg = nullptr;
    cudaGetSymbolAddress((void**)&gx,   g_x);
    cudaGetSymbolAddress((void**)&gh,   g_h);
    cudaGetSymbolAddress((void**)&gdeg, g_deg);

    const int smem_bytes = (2 * D * D + 2 * BM * D) * sizeof(float); // 192 KB
    cudaFuncSetAttribute(k_mlp, cudaFuncAttributeMaxDynamicSharedMemorySize, smem_bytes);

    const int edge_blocks = (NEDGES + THREADS - 1) / THREADS;
    const int gath_blocks = (NNODES * 32 + THREADS - 1) / THREADS;
    const int mlp_blocks  = (NNODES + BM - 1) / BM;

    // ---- CSR build (amortized over both layers) ----
    cudaMemsetAsync(gdeg, 0, NNODES * sizeof(int));           // 1
    k_hist<<<edge_blocks, THREADS>>>(dst);                    // 2
    k_scan<<<1, 1024>>>();                                    // 3
    k_fill<<<edge_blocks, THREADS>>>(src, dst);               // 4

    // ---- layer 1 ----
    k_gather<<<gath_blocks, THREADS>>>(inputs, gx);           // 5
    k_mlp<<<mlp_blocks, THREADS, smem_bytes>>>(gx, W1a, b1a, W1b, b1b, gh, 1);  // 6 (ncu -s 5)

    // ---- layer 2 ----
    k_gather<<<gath_blocks, THREADS>>>(gh, gx);               // 7
    k_mlp<<<mlp_blocks, THREADS, smem_bytes>>>(gx, W2a, b2a, W2b, b2b, out, 0); // 8
}

// round 4
// speedup vs baseline: 1.8794x; 1.6554x over previous
#include <cuda_runtime.h>
#include <cuda_bf16.h>
#include <cstdint>

#define D 128
#define NNODES 50000
#define NEDGES 600000
#define THREADS 256

// ---------------------------------------------------------------------------
// Device-global scratch (allocation-free rule)
// ---------------------------------------------------------------------------
__device__ float g_x[(size_t)NNODES * D];
__device__ float g_h[(size_t)NNODES * D];
__device__ int   g_deg[NNODES];
__device__ int   g_off[NNODES + 1];
__device__ int   g_cursor[NNODES];
__device__ int   g_adj[NEDGES];
// split weights, K-major [n][k], 4 matrices: W1a, W1b, W2a, W2b
__device__ __nv_bfloat16 g_whi[4 * D * D];
__device__ __nv_bfloat16 g_wlo[4 * D * D];

// ---------------------------------------------------------------------------
// helpers
// ---------------------------------------------------------------------------
__device__ __forceinline__ uint32_t smem_u32(const void* p) {
    uint32_t a;
    asm("{ .reg .u64 t; cvta.to.shared.u64 t, %1; cvt.u32.u64 %0, t; }" : "=r"(a) : "l"(p));
    return a;
}

__device__ __forceinline__ void ldsm_x4(uint32_t& r0, uint32_t& r1, uint32_t& r2, uint32_t& r3,
                                        uint32_t addr) {
    asm volatile("ldmatrix.sync.aligned.m8n8.x4.shared.b16 {%0,%1,%2,%3}, [%4];"
                 : "=r"(r0), "=r"(r1), "=r"(r2), "=r"(r3) : "r"(addr));
}

__device__ __forceinline__ void mma_bf16(float& c0, float& c1, float& c2, float& c3,
                                         uint32_t a0, uint32_t a1, uint32_t a2, uint32_t a3,
                                         uint32_t b0, uint32_t b1) {
    asm volatile("mma.sync.aligned.m16n8k16.row.col.f32.bf16.bf16.f32 "
                 "{%0,%1,%2,%3}, {%4,%5,%6,%7}, {%8,%9}, {%0,%1,%2,%3};"
                 : "+f"(c0), "+f"(c1), "+f"(c2), "+f"(c3)
                 : "r"(a0), "r"(a1), "r"(a2), "r"(a3), "r"(b0), "r"(b1));
}

__device__ __forceinline__ void split2(float v0, float v1, uint32_t& hi2, uint32_t& lo2) {
    __nv_bfloat16 h0 = __float2bfloat16(v0), h1 = __float2bfloat16(v1);
    __nv_bfloat16 l0 = __float2bfloat16(v0 - __bfloat162float(h0));
    __nv_bfloat16 l1 = __float2bfloat16(v1 - __bfloat162float(h1));
    __nv_bfloat162 hp; hp.x = h0; hp.y = h1;
    __nv_bfloat162 lp; lp.x = l0; lp.y = l1;
    hi2 = *(uint32_t*)&hp;
    lo2 = *(uint32_t*)&lp;
}

// ---------------------------------------------------------------------------
// CSR build
// ---------------------------------------------------------------------------
__global__ void k_hist(const int* __restrict__ dst) {
    int e = blockIdx.x * blockDim.x + threadIdx.x;
    if (e < NEDGES) atomicAdd(&g_deg[dst[e]], 1);
}

__global__ __launch_bounds__(1024, 1)
void k_scan() {
    __shared__ int warp_sums[32];
    __shared__ int carry_s;
    const int tid = threadIdx.x, lane = tid & 31, wid = tid >> 5;
    if (tid == 0) carry_s = 0;
    __syncthreads();
    for (int base = 0; base < NNODES; base += 1024) {
        int i = base + tid;
        int v = (i < NNODES) ? g_deg[i] : 0;
        if (i < NNODES) g_deg[i] = 0;      // re-zero for next call
        int s = v;
        #pragma unroll
        for (int o = 1; o < 32; o <<= 1) {
            int t = __shfl_up_sync(0xFFFFFFFFu, s, o);
            if (lane >= o) s += t;
        }
        if (lane == 31) warp_sums[wid] = s;
        __syncthreads();
        if (wid == 0) {
            int ws = warp_sums[lane];
            #pragma unroll
            for (int o = 1; o < 32; o <<= 1) {
                int t = __shfl_up_sync(0xFFFFFFFFu, ws, o);
                if (lane >= o) ws += t;
            }
            warp_sums[lane] = ws;
        }
        __syncthreads();
        int carry = carry_s;
        int excl = carry + (wid ? warp_sums[wid - 1] : 0) + s - v;
        if (i < NNODES) { g_off[i] = excl; g_cursor[i] = excl; }
        __syncthreads();
        if (tid == 1023) carry_s = carry + warp_sums[31];
        __syncthreads();
    }
    if (tid == 0) g_off[NNODES] = carry_s;
}

__global__ void k_fill(const int* __restrict__ src, const int* __restrict__ dst) {
    int e = blockIdx.x * blockDim.x + threadIdx.x;
    if (e < NEDGES) {
        int pos = atomicAdd(&g_cursor[dst[e]], 1);
        g_adj[pos] = src[e];
    }
}

// ---------------------------------------------------------------------------
// weight transpose + bf16 split: out[n][k] = split(W[k][n])
// ---------------------------------------------------------------------------
__global__ void k_wsplit(const float* __restrict__ W0, const float* __restrict__ W1,
                         const float* __restrict__ W2, const float* __restrict__ W3) {
    const float* W = (blockIdx.y == 0) ? W0 : (blockIdx.y == 1) ? W1 : (blockIdx.y == 2) ? W2 : W3;
    __nv_bfloat16* hi = g_whi + blockIdx.y * D * D;
    __nv_bfloat16* lo = g_wlo + blockIdx.y * D * D;
    int idx = blockIdx.x * blockDim.x + threadIdx.x;
    if (idx < D * D) {
        int n = idx >> 7, k = idx & 127;
        float w = W[k * D + n];
        __nv_bfloat16 h = __float2bfloat16(w);
        hi[idx] = h;
        lo[idx] = __float2bfloat16(w - __bfloat162float(h));
    }
}

// ---------------------------------------------------------------------------
// gather: x[i] = h[i] + sum_{s in adj(i)} h[s]   (one warp per node)
// ---------------------------------------------------------------------------
__global__ __launch_bounds__(THREADS)
void k_gather(const float* __restrict__ h, float* __restrict__ x) {
    int warp = (blockIdx.x * blockDim.x + threadIdx.x) >> 5;
    int lane = threadIdx.x & 31;
    if (warp >= NNODES) return;
    const float4* hp = (const float4*)h;
    int beg = g_off[warp], end = g_off[warp + 1];
    float4 acc = hp[(size_t)warp * 32 + lane];
    int p = beg;
    for (; p + 4 <= end; p += 4) {
        int s0 = g_adj[p], s1 = g_adj[p + 1], s2 = g_adj[p + 2], s3 = g_adj[p + 3];
        float4 v0 = hp[(size_t)s0 * 32 + lane];
        float4 v1 = hp[(size_t)s1 * 32 + lane];
        float4 v2 = hp[(size_t)s2 * 32 + lane];
        float4 v3 = hp[(size_t)s3 * 32 + lane];
        acc.x += v0.x + v1.x + v2.x + v3.x;
        acc.y += v0.y + v1.y + v2.y + v3.y;
        acc.z += v0.z + v1.z + v2.z + v3.z;
        acc.w += v0.w + v1.w + v2.w + v3.w;
    }
    for (; p < end; ++p) {
        int s = g_adj[p];
        float4 v = hp[(size_t)s * 32 + lane];
        acc.x += v.x; acc.y += v.y; acc.z += v.z; acc.w += v.w;
    }
    ((float4*)x)[(size_t)warp * 32 + lane] = acc;
}

// ---------------------------------------------------------------------------
// HMMA fused MLP: out = maybe_relu( relu(x@Wa+ba) @ Wb + bb )
// bf16x3 split (hi*hi + lo*hi + hi*lo), fp32 accum, mma.sync.m16n8k16
// Per CTA: 128 rows. 8 warps in 4(m) x 2(n) grid; warp tile 32x64.
// smem rows padded to 272 B (136 bf16) -> conflict-free ldmatrix.
// ---------------------------------------------------------------------------
#define PB 272                               // row pitch in bytes (136 bf16)
#define SMEM_BA   0
#define SMEM_BB   512
#define SMEM_AHI  1024
#define ABUF_SZ   (128 * PB)                 // 34816 B
#define SMEM_ALO  (SMEM_AHI + ABUF_SZ)
#define SMEM_W    (SMEM_ALO + ABUF_SZ)       // 4 x ABUF_SZ: Wa_hi, Wa_lo, Wb_hi, Wb_lo
#define SMEM_TOTAL (SMEM_W + 4 * ABUF_SZ)    // 209920 B

__global__ __launch_bounds__(THREADS, 1)
void k_mlp_hmma(const float* __restrict__ x,
                const __nv_bfloat16* __restrict__ wa_hi, const __nv_bfloat16* __restrict__ wa_lo,
                const __nv_bfloat16* __restrict__ wb_hi, const __nv_bfloat16* __restrict__ wb_lo,
                const float* __restrict__ ba, const float* __restrict__ bb,
                float* __restrict__ out, int relu_out) {
    extern __shared__ char smem[];
    const uint32_t sb = smem_u32(smem);
    const int tid = threadIdx.x, wid = tid >> 5, lane = tid & 31;
    const int row0 = blockIdx.x * 128;

    // ---- biases ----
    if (tid < 128) {
        ((float*)(smem + SMEM_BA))[tid] = ba[tid];
        ((float*)(smem + SMEM_BB))[tid] = bb[tid];
    }

    // ---- weights -> padded smem (16B chunks) ----
    {
        const __nv_bfloat16* Wp[4] = {wa_hi, wa_lo, wb_hi, wb_lo};
        #pragma unroll 4
        for (int i = tid; i < 4 * 128 * 16; i += THREADS) {
            int mat = i >> 11;
            int rem = i & 2047;
            int row = rem >> 4;
            int ch  = rem & 15;
            uint4 v = ((const uint4*)Wp[mat])[(row << 4) + ch];
            *(uint4*)(smem + SMEM_W + mat * ABUF_SZ + row * PB + ch * 16) = v;
        }
    }

    // ---- A tile: load fp32, split to bf16 hi/lo ----
    {
        int r  = tid >> 1;
        int c0 = (tid & 1) * 64;
        int grow = row0 + r;
        char* hi = smem + SMEM_AHI + r * PB + c0 * 2;
        char* lo = smem + SMEM_ALO + r * PB + c0 * 2;
        if (grow < NNODES) {
            const float4* xp = (const float4*)(x + (size_t)grow * D + c0);
            #pragma unroll
            for (int c = 0; c < 64; c += 4) {
                float4 v = xp[c >> 2];
                uint32_t h2a, l2a, h2b, l2b;
                split2(v.x, v.y, h2a, l2a);
                split2(v.z, v.w, h2b, l2b);
                *(uint32_t*)(hi + c * 2)     = h2a;
                *(uint32_t*)(hi + c * 2 + 4) = h2b;
                *(uint32_t*)(lo + c * 2)     = l2a;
                *(uint32_t*)(lo + c * 2 + 4) = l2b;
            }
        } else {
            #pragma unroll
            for (int c = 0; c < 64; c += 4) {
                *(uint32_t*)(hi + c * 2)     = 0u;
                *(uint32_t*)(hi + c * 2 + 4) = 0u;
                *(uint32_t*)(lo + c * 2)     = 0u;
                *(uint32_t*)(lo + c * 2 + 4) = 0u;
            }
        }
    }
    __syncthreads();

    // warp tiling
    const int warp_m = wid & 3;           // 0..3 -> m0 = warp_m*32
    const int warp_n = wid >> 2;          // 0..1 -> n0 = warp_n*64
    const int m0 = warp_m * 32;
    const int n0 = warp_n * 64;

    // per-lane ldmatrix address offsets (within a tile buffer)
    // A x4: lanes 0-15 -> rows 0-15 at kbyte 0; lanes 16-31 -> rows 0-15 at kbyte 16
    const uint32_t a_off = (uint32_t)((m0 + (lane & 15)) * PB + (lane >> 4) * 16);
    // B x4: group g=lane>>3: n += (g>>1)*8 + lane&7 ; kbyte = (g&1)*16
    const uint32_t b_off = (uint32_t)((n0 + ((lane >> 4) << 3) + (lane & 7)) * PB
                                      + ((lane >> 3) & 1) * 16);

    const uint32_t Ahi = sb + SMEM_AHI;
    const uint32_t Alo = sb + SMEM_ALO;

    float acc[2][8][4];

    // =================== GEMM pass macro-ish lambda ===================
    auto run_gemm = [&](uint32_t Bhi, uint32_t Blo) {
        #pragma unroll
        for (int tm = 0; tm < 2; tm++)
            #pragma unroll
            for (int tn = 0; tn < 8; tn++)
                #pragma unroll
                for (int q = 0; q < 4; q++) acc[tm][tn][q] = 0.f;

        #pragma unroll
        for (int s = 0; s < 8; s++) {
            const uint32_t kb = s * 32;
            uint32_t ah[2][4], al[2][4];
            ldsm_x4(ah[0][0], ah[0][1], ah[0][2], ah[0][3], Ahi + a_off + kb);
            ldsm_x4(ah[1][0], ah[1][1], ah[1][2], ah[1][3], Ahi + a_off + 16 * PB + kb);
            ldsm_x4(al[0][0], al[0][1], al[0][2], al[0][3], Alo + a_off + kb);
            ldsm_x4(al[1][0], al[1][1], al[1][2], al[1][3], Alo + a_off + 16 * PB + kb);

            uint32_t bh[4][4], bl[4][4];
            #pragma unroll
            for (int p = 0; p < 4; p++) {
                ldsm_x4(bh[p][0], bh[p][1], bh[p][2], bh[p][3], Bhi + b_off + p * 16 * PB + kb);
                ldsm_x4(bl[p][0], bl[p][1], bl[p][2], bl[p][3], Blo + b_off + p * 16 * PB + kb);
            }

            #pragma unroll
            for (int tm = 0; tm < 2; tm++) {
                #pragma unroll
                for (int p = 0; p < 4; p++) {
                    #pragma unroll
                    for (int half = 0; half < 2; half++) {
                        const int tn = p * 2 + half;
                        float* c = acc[tm][tn];
                        // hi*hi
                        mma_bf16(c[0], c[1], c[2], c[3],
                                 ah[tm][0], ah[tm][1], ah[tm][2], ah[tm][3],
                                 bh[p][half * 2], bh[p][half * 2 + 1]);
                        // lo*hi
                        mma_bf16(c[0], c[1], c[2], c[3],
                                 al[tm][0], al[tm][1], al[tm][2], al[tm][3],
                                 bh[p][half * 2], bh[p][half * 2 + 1]);
                        // hi*lo
                        mma_bf16(c[0], c[1], c[2], c[3],
                                 ah[tm][0], ah[tm][1], ah[tm][2], ah[tm][3],
                                 bl[p][half * 2], bl[p][half * 2 + 1]);
                    }
                }
            }
        }
    };

    // ---- GEMM1: A @ Wa ----
    run_gemm(sb + SMEM_W + 0 * ABUF_SZ, sb + SMEM_W + 1 * ABUF_SZ);
    __syncthreads();   // everyone done reading A buffers

    // ---- epilogue 1: H = split(relu(acc + ba)) -> A buffers ----
    {
        const float* bav = (const float*)(smem + SMEM_BA);
        #pragma unroll
        for (int tm = 0; tm < 2; tm++) {
            #pragma unroll
            for (int tn = 0; tn < 8; tn++) {
                const int col = n0 + tn * 8 + (lane & 3) * 2;
                const float b0v = bav[col], b1v = bav[col + 1];
                const int r_lo = m0 + tm * 16 + (lane >> 2);
                float v0 = fmaxf(acc[tm][tn][0] + b0v, 0.f);
                float v1 = fmaxf(acc[tm][tn][1] + b1v, 0.f);
                float v2 = fmaxf(acc[tm][tn][2] + b0v, 0.f);
                float v3 = fmaxf(acc[tm][tn][3] + b1v, 0.f);
                uint32_t h2, l2;
                split2(v0, v1, h2, l2);
                *(uint32_t*)(smem + SMEM_AHI + r_lo * PB + col * 2) = h2;
                *(uint32_t*)(smem + SMEM_ALO + r_lo * PB + col * 2) = l2;
                split2(v2, v3, h2, l2);
                *(uint32_t*)(smem + SMEM_AHI + (r_lo + 8) * PB + col * 2) = h2;
                *(uint32_t*)(smem + SMEM_ALO + (r_lo + 8) * PB + col * 2) = l2;
            }
        }
    }
    __syncthreads();

    // ---- GEMM2: H @ Wb ----
    run_gemm(sb + SMEM_W + 2 * ABUF_SZ, sb + SMEM_W + 3 * ABUF_SZ);

    // ---- epilogue 2: out = maybe_relu(acc + bb) ----
    {
        const float* bbv = (const float*)(smem + SMEM_BB);
        #pragma unroll
        for (int tm = 0; tm < 2; tm++) {
            #pragma unroll
            for (int tn = 0; tn < 8; tn++) {
                const int col = n0 + tn * 8 + (lane & 3) * 2;
                const float b0v = bbv[col], b1v = bbv[col + 1];
                const int r_lo = row0 + m0 + tm * 16 + (lane >> 2);
                float v0 = acc[tm][tn][0] + b0v;
                float v1 = acc[tm][tn][1] + b1v;
                float v2 = acc[tm][tn][2] + b0v;
                float v3 = acc[tm][tn][3] + b1v;
                if (relu_out) {
                    v0 = fmaxf(v0, 0.f); v1 = fmaxf(v1, 0.f);
                    v2 = fmaxf(v2, 0.f); v3 = fmaxf(v3, 0.f);
                }
                if (r_lo < NNODES)
                    *(float2*)(out + (size_t)r_lo * D + col) = make_float2(v0, v1);
                if (r_lo + 8 < NNODES)
                    *(float2*)(out + (size_t)(r_lo + 8) * D + col) = make_float2(v2, v3);
            }
        }
    }
}

// ---------------------------------------------------------------------------
// launch
// ---------------------------------------------------------------------------
extern "C" void kernel_launch(void* const* d_in, const int* in_sizes, int n_in,
                              void* d_out, int out_size) {
    const float* inputs = (const float*)d_in[0];
    const int*   src    = (const int*)  d_in[1];
    const int*   dst    = (const int*)  d_in[2];
    const float* W1a    = (const float*)d_in[3];
    const float* b1a    = (const float*)d_in[4];
    const float* W1b    = (const float*)d_in[5];
    const float* b1b    = (const float*)d_in[6];
    const float* W2a    = (const float*)d_in[7];
    const float* b2a    = (const float*)d_in[8];
    const float* W2b    = (const float*)d_in[9];
    const float* b2b    = (const float*)d_in[10];
    float* out = (float*)d_out;

    float *gx = nullptr, *gh = nullptr;
    __nv_bfloat16 *gwhi = nullptr, *gwlo = nullptr;
    cudaGetSymbolAddress((void**)&gx, g_x);
    cudaGetSymbolAddress((void**)&gh, g_h);
    cudaGetSymbolAddress((void**)&gwhi, g_whi);
    cudaGetSymbolAddress((void**)&gwlo, g_wlo);

    cudaFuncSetAttribute(k_mlp_hmma, cudaFuncAttributeMaxDynamicSharedMemorySize, SMEM_TOTAL);

    const int edge_blocks = (NEDGES + THREADS - 1) / THREADS;
    const int gath_blocks = (NNODES * 32 + THREADS - 1) / THREADS;
    const int mlp_blocks  = (NNODES + 127) / 128;

    // CSR build (g_deg starts zero; k_scan re-zeroes it each call)
    k_hist<<<edge_blocks, THREADS>>>(dst);                       // 1
    k_scan<<<1, 1024>>>();                                       // 2
    k_fill<<<edge_blocks, THREADS>>>(src, dst);                  // 3
    k_wsplit<<<dim3(64, 4), 256>>>(W1a, W1b, W2a, W2b);          // 4

    // layer 1: matrices 0 (W1a) and 1 (W1b)
    k_gather<<<gath_blocks, THREADS>>>(inputs, gx);              // 5
    k_mlp_hmma<<<mlp_blocks, THREADS, SMEM_TOTAL>>>(             // 6  (ncu -s 5)
        gx, gwhi + 0 * D * D, gwlo + 0 * D * D,
            gwhi + 1 * D * D, gwlo + 1 * D * D,
        b1a, b1b, gh, 1);

    // layer 2: matrices 2 (W2a) and 3 (W2b)
    k_gather<<<gath_blocks, THREADS>>>(gh, gx);                  // 7
    k_mlp_hmma<<<mlp_blocks, THREADS, SMEM_TOTAL>>>(
        gx, gwhi + 2 * D * D, gwlo + 2 * D * D,
            gwhi + 3 * D * D, gwlo + 3 * D * D,
        b2a, b2b, out, 0);
}